// round 16
// baseline (speedup 1.0000x reference)
#include <cuda_runtime.h>
#include <cuda_fp16.h>
#include <math.h>

#define Nn 4096
#define INF_ 512
#define Hh 128
#define OUTd 40
#define CAP 128
#define ITFIX 46          // fixed Picard iterations (even -> final in buf 0)
#define KAPPAf 0.8f
#define LNEPS 1e-5f
#define CH 256            // chunks per column for sparse extraction
#define RPC (Nn / CH)     // rows per chunk (16)
#define SLOTS 8           // candidate slots per (column, chunk)

// ---------------- device scratch (no allocations allowed) ----------------
__device__ float g_h[Nn * Hh];        // encoder output, node-major
__device__ float g_T[Nn * Hh];        // Omega1 @ U, node-major
__device__ float g_B[Nn * Hh];        // bias term B, node-major
__device__ __half g_Xh[2 * Nn * Hh];  // ping-pong X, node-major, fp16
__device__ float g_Wpt[Hh * Hh];      // Wp transposed
__device__ float g_O1t[Hh * Hh];      // Omega1 transposed
__device__ float g_WencT[INF_ * Hh];  // W_enc transposed [IN][H]
__device__ int   g_cntC[Nn * CH];     // counts, column-major-per-j [j][c]
__device__ int2  g_cand[Nn * CH * SLOTS]; // padded candidates [j][c][s]
__device__ int   g_ccnt[Nn];
__device__ int2  g_cpk[Nn * CAP];     // packed (index, value-bits)
__device__ unsigned g_bar_count;
__device__ volatile unsigned g_bar_gen;

// ---------------- software grid barrier (all blocks resident) ----------------
__device__ __forceinline__ void grid_sync(unsigned nb) {
    __syncthreads();
    if (threadIdx.x == 0) {
        unsigned gen = g_bar_gen;
        __threadfence();
        if (atomicAdd(&g_bar_count, 1u) == nb - 1u) {
            g_bar_count = 0u;
            __threadfence();
            g_bar_gen = gen + 1u;
        } else {
            while (g_bar_gen == gen) { __nanosleep(64); }
        }
        __threadfence();
    }
    __syncthreads();
}

__device__ __forceinline__ void bar_group(int g) {
    asm volatile("bar.sync %0, %1;" :: "r"(g + 1), "r"(128) : "memory");
}

// ---------------- setup: X0 transpose (tiled), Wenc^T, O1^T, barrier ----------------
__global__ void __launch_bounds__(256) k_setup(const float* __restrict__ X0,
                                               const float* __restrict__ Wenc,
                                               const float* __restrict__ O1) {
    int b = blockIdx.x;
    int t = threadIdx.x;
    if (b < 128) {
        // transpose a 128i x 32j tile of X0[H][N] into g_Xh[j][i] (fp16)
        __shared__ float ts_[32 * 129];
        int j0 = b * 32;
#pragma unroll
        for (int rep = 0; rep < 16; rep++) {
            int e = rep * 256 + t;
            int i = e >> 5, jj = e & 31;
            ts_[jj * 129 + i] = X0[(size_t)i * Nn + j0 + jj];
        }
        __syncthreads();
#pragma unroll
        for (int rep = 0; rep < 16; rep++) {
            int e = rep * 256 + t;
            int jj = e >> 7, i = e & 127;
            g_Xh[(size_t)(j0 + jj) * Hh + i] = __float2half(ts_[jj * 129 + i]);
        }
    } else if (b < 448) {
        int e = (b - 128) * 256 + t;
        if (e < INF_ * Hh) {
            int k = e >> 7, i = e & 127;
            g_WencT[e] = Wenc[(size_t)i * INF_ + k];
        } else {
            int e2 = e - INF_ * Hh;   // < 16384
            int m = e2 >> 7, i = e2 & 127;
            g_O1t[e2] = O1[i * Hh + m];
        }
    } else {
        if (t == 0) { g_bar_count = 0u; g_bar_gen = 0u; }
    }
}

// ---------------- L1-ball row projection via Michelot (exact) ----------------
__global__ void __launch_bounds__(128) k_proj(const float* __restrict__ W) {
    int row = blockIdx.x * 4 + (threadIdx.x >> 5);
    int lane = threadIdx.x & 31;
    float w0[4], a[4];
    float sum = 0.f;
#pragma unroll
    for (int q = 0; q < 4; q++) {
        w0[q] = W[row * Hh + q * 32 + lane];
        a[q] = fabsf(w0[q]);
        sum += a[q];
    }
#pragma unroll
    for (int o = 16; o > 0; o >>= 1) sum += __shfl_xor_sync(0xffffffffu, sum, o);
    bool doproj = sum > KAPPAf;
    float theta = 0.f;
    if (doproj) {
        float th = (sum - KAPPAf) * (1.f / 128.f);
        int prev = -1;
        for (int it = 0; it < 130; it++) {
            float s = 0.f; int c = 0;
#pragma unroll
            for (int q = 0; q < 4; q++) if (a[q] > th) { s += a[q]; c++; }
#pragma unroll
            for (int o = 16; o > 0; o >>= 1) {
                s += __shfl_xor_sync(0xffffffffu, s, o);
                c += __shfl_xor_sync(0xffffffffu, c, o);
            }
            th = (s - KAPPAf) / (float)c;
            if (c == prev) break;
            prev = c;
        }
        theta = th;
    }
#pragma unroll
    for (int q = 0; q < 4; q++) {
        float p = doproj ? copysignf(fmaxf(a[q] - theta, 0.f), w0[q]) : w0[q];
        g_Wpt[(q * 32 + lane) * Hh + row] = p;
    }
}

// ---------------- sparse CSC extraction, single adj scan, batched loads ----------------
__global__ void k_scan(const float* __restrict__ adj) {
    int t = blockIdx.x * blockDim.x + threadIdx.x;   // (Nn/4)*CH threads
    if (t >= (Nn / 4) * CH) return;
    int j4 = t & (Nn / 4 - 1);
    int c = t >> 10;
    const float4* a4 = (const float4*)adj;
    int k0 = c * RPC;
    int j = j4 * 4;
    int b0 = (j + 0) * CH * SLOTS + c * SLOTS, s0 = 0;
    int b1 = (j + 1) * CH * SLOTS + c * SLOTS, s1 = 0;
    int b2 = (j + 2) * CH * SLOTS + c * SLOTS, s2 = 0;
    int b3 = (j + 3) * CH * SLOTS + c * SLOTS, s3 = 0;
    for (int kk = 0; kk < RPC; kk += 4) {
        float4 v[4];
#pragma unroll
        for (int u = 0; u < 4; u++)
            v[u] = __ldg(&a4[(size_t)(k0 + kk + u) * (Nn / 4) + j4]);
#pragma unroll
        for (int u = 0; u < 4; u++) {
            int k = k0 + kk + u;
            if (v[u].x != 0.f) { if (s0 < SLOTS) g_cand[b0 + s0] = make_int2(k, __float_as_int(v[u].x)); s0++; }
            if (v[u].y != 0.f) { if (s1 < SLOTS) g_cand[b1 + s1] = make_int2(k, __float_as_int(v[u].y)); s1++; }
            if (v[u].z != 0.f) { if (s2 < SLOTS) g_cand[b2 + s2] = make_int2(k, __float_as_int(v[u].z)); s2++; }
            if (v[u].w != 0.f) { if (s3 < SLOTS) g_cand[b3 + s3] = make_int2(k, __float_as_int(v[u].w)); s3++; }
        }
    }
    g_cntC[(j + 0) * CH + c] = s0 > SLOTS ? SLOTS : s0;
    g_cntC[(j + 1) * CH + c] = s1 > SLOTS ? SLOTS : s1;
    g_cntC[(j + 2) * CH + c] = s2 > SLOTS ? SLOTS : s2;
    g_cntC[(j + 3) * CH + c] = s3 > SLOTS ? SLOTS : s3;
}

// ---------------- fused offsets (warp prefix scan) + compaction ----------------
__global__ void __launch_bounds__(256) k_offcmp() {
    int j = blockIdx.x * 8 + (threadIdx.x >> 5);
    int lane = threadIdx.x & 31;
    int cnts[8], offs[8];
    int base = 0;
#pragma unroll
    for (int q = 0; q < 8; q++) {
        int c = q * 32 + lane;
        int v = g_cntC[j * CH + c];     // coalesced (c fast within warp)
        cnts[q] = v;
        int incl = v;
#pragma unroll
        for (int o = 1; o < 32; o <<= 1) {
            int u = __shfl_up_sync(0xffffffffu, incl, o);
            if (lane >= o) incl += u;
        }
        offs[q] = base + incl - v;
        base += __shfl_sync(0xffffffffu, incl, 31);
    }
    if (lane == 0) g_ccnt[j] = base > CAP ? CAP : base;
#pragma unroll
    for (int q = 0; q < 8; q++) {
        int c = q * 32 + lane;
        int src = (j * CH + c) * SLOTS;
        int o = offs[q];
        for (int p = 0; p < cnts[q]; p++) {
            if (o + p < CAP) g_cpk[j * CAP + o + p] = g_cand[src + p];
        }
    }
}

// ---------------- encoder: h = gelu(LN(x @ W_enc^T + b_enc)) ----------------
// 256 threads = 2 groups x 128 channels; 16 nodes/block (halves WencT L2 traffic)
__global__ void __launch_bounds__(256) k_enc(const float* __restrict__ x,
                                             const float* __restrict__ benc,
                                             const float* __restrict__ lng,
                                             const float* __restrict__ lnb) {
    __shared__ float xs[16 * INF_];   // 32 KB
    __shared__ float rs[8], rq[8];
    int t = threadIdx.x;
    int i = t & 127;
    int grp = t >> 7;                 // 0 or 1
    int jb = blockIdx.x * 16 + grp * 8;
    for (int n = 0; n < 8; n++)
        for (int k = i; k < INF_; k += 128)
            xs[(grp * 8 + n) * INF_ + k] = x[(size_t)(jb + n) * INF_ + k];
    __syncthreads();
    float acc[8];
    float bi = benc[i];
#pragma unroll
    for (int n = 0; n < 8; n++) acc[n] = bi;
    const float4* xs4 = (const float4*)(xs + grp * 8 * INF_);
    for (int k4 = 0; k4 < INF_ / 4; k4++) {
        float w0 = g_WencT[(4 * k4 + 0) * Hh + i];
        float w1 = g_WencT[(4 * k4 + 1) * Hh + i];
        float w2 = g_WencT[(4 * k4 + 2) * Hh + i];
        float w3 = g_WencT[(4 * k4 + 3) * Hh + i];
#pragma unroll
        for (int n = 0; n < 8; n++) {
            float4 xv = xs4[n * (INF_ / 4) + k4];
            acc[n] += w0 * xv.x + w1 * xv.y + w2 * xv.z + w3 * xv.w;
        }
    }
    float gi = lng[i], bbi = lnb[i];
    int lane = t & 31, wid = t >> 5;  // wid 0..7
    for (int n = 0; n < 8; n++) {
        float s = acc[n], q = acc[n] * acc[n];
#pragma unroll
        for (int o = 16; o > 0; o >>= 1) {
            s += __shfl_xor_sync(0xffffffffu, s, o);
            q += __shfl_xor_sync(0xffffffffu, q, o);
        }
        if (lane == 0) { rs[wid] = s; rq[wid] = q; }
        __syncthreads();
        int w0 = grp * 4;
        float ts = rs[w0] + rs[w0 + 1] + rs[w0 + 2] + rs[w0 + 3];
        float tq = rq[w0] + rq[w0 + 1] + rq[w0 + 2] + rq[w0 + 3];
        float mu = ts * (1.f / 128.f);
        float var = tq * (1.f / 128.f) - mu * mu;
        float v = (acc[n] - mu) * rsqrtf(var + LNEPS) * gi + bbi;
        float ge = 0.5f * v * (1.f + erff(v * 0.70710678118654752f));
        g_h[(size_t)(jb + n) * Hh + i] = ge;
        __syncthreads();
    }
}

// ---------------- persistent fixed-point kernel + fused epilogue ----------------
#define NBLK 256
#define FP_SMEM ((Hh * Hh + 4 * 4 * Hh) * (int)sizeof(float))

extern __shared__ float dsm[];

// fp32 warp-per-node float4 gather (B precompute)
__device__ __forceinline__ float4 gather_row(const float4* __restrict__ S4,
                                             int j, int lane) {
    int cnt = g_ccnt[j];
    const int2* cp = g_cpk + j * CAP;
    float4 acc = make_float4(0.f, 0.f, 0.f, 0.f);
    int p = 0;
    for (; p + 4 <= cnt; p += 4) {
        int2 e0 = __ldg(cp + p);
        int2 e1 = __ldg(cp + p + 1);
        int2 e2 = __ldg(cp + p + 2);
        int2 e3 = __ldg(cp + p + 3);
        float4 v0 = __ldg(&S4[(size_t)e0.x * 32 + lane]);
        float4 v1 = __ldg(&S4[(size_t)e1.x * 32 + lane]);
        float4 v2 = __ldg(&S4[(size_t)e2.x * 32 + lane]);
        float4 v3 = __ldg(&S4[(size_t)e3.x * 32 + lane]);
        float w0 = __int_as_float(e0.y), w1 = __int_as_float(e1.y);
        float w2 = __int_as_float(e2.y), w3 = __int_as_float(e3.y);
        acc.x += w0 * v0.x; acc.y += w0 * v0.y; acc.z += w0 * v0.z; acc.w += w0 * v0.w;
        acc.x += w1 * v1.x; acc.y += w1 * v1.y; acc.z += w1 * v1.z; acc.w += w1 * v1.w;
        acc.x += w2 * v2.x; acc.y += w2 * v2.y; acc.z += w2 * v2.z; acc.w += w2 * v2.w;
        acc.x += w3 * v3.x; acc.y += w3 * v3.y; acc.z += w3 * v3.z; acc.w += w3 * v3.w;
    }
    for (; p < cnt; p++) {
        int2 e = __ldg(cp + p);
        float4 v = __ldg(&S4[(size_t)e.x * 32 + lane]);
        float w = __int_as_float(e.y);
        acc.x += w * v.x; acc.y += w * v.y; acc.z += w * v.z; acc.w += w * v.w;
    }
    return acc;
}

// fp16 gather: lane owns channels 4*lane..4*lane+3 (one uint2 per row)
__device__ __forceinline__ float4 hload4(const uint2* __restrict__ S2, size_t idx) {
    uint2 u = __ldg(&S2[idx]);
    __half2 h0 = *reinterpret_cast<__half2*>(&u.x);
    __half2 h1 = *reinterpret_cast<__half2*>(&u.y);
    float2 f0 = __half22float2(h0);
    float2 f1 = __half22float2(h1);
    return make_float4(f0.x, f0.y, f1.x, f1.y);
}

__device__ __forceinline__ float4 gather_row_h(const uint2* __restrict__ S2,
                                               int j, int lane) {
    int cnt = g_ccnt[j];
    const int2* cp = g_cpk + j * CAP;
    float4 acc = make_float4(0.f, 0.f, 0.f, 0.f);
    int p = 0;
    for (; p + 4 <= cnt; p += 4) {
        int2 e0 = __ldg(cp + p);
        int2 e1 = __ldg(cp + p + 1);
        int2 e2 = __ldg(cp + p + 2);
        int2 e3 = __ldg(cp + p + 3);
        float4 v0 = hload4(S2, (size_t)e0.x * 32 + lane);
        float4 v1 = hload4(S2, (size_t)e1.x * 32 + lane);
        float4 v2 = hload4(S2, (size_t)e2.x * 32 + lane);
        float4 v3 = hload4(S2, (size_t)e3.x * 32 + lane);
        float w0 = __int_as_float(e0.y), w1 = __int_as_float(e1.y);
        float w2 = __int_as_float(e2.y), w3 = __int_as_float(e3.y);
        acc.x += w0 * v0.x; acc.y += w0 * v0.y; acc.z += w0 * v0.z; acc.w += w0 * v0.w;
        acc.x += w1 * v1.x; acc.y += w1 * v1.y; acc.z += w1 * v1.z; acc.w += w1 * v1.w;
        acc.x += w2 * v2.x; acc.y += w2 * v2.y; acc.z += w2 * v2.z; acc.w += w2 * v2.w;
        acc.x += w3 * v3.x; acc.y += w3 * v3.y; acc.z += w3 * v3.z; acc.w += w3 * v3.w;
    }
    for (; p < cnt; p++) {
        int2 e = __ldg(cp + p);
        float4 v = hload4(S2, (size_t)e.x * 32 + lane);
        float w = __int_as_float(e.y);
        acc.x += w * v.x; acc.y += w * v.y; acc.z += w * v.z; acc.w += w * v.w;
    }
    return acc;
}

__global__ void __launch_bounds__(512, 2) k_fp(const float* __restrict__ Wv,
                                               const float* __restrict__ bv,
                                               const float* __restrict__ lng,
                                               const float* __restrict__ lnb,
                                               float* __restrict__ out) {
    float* Wsm = dsm;
    float* sb = dsm + Hh * Hh;
    __shared__ float s_red[4][32];
    const int tid = threadIdx.x;
    const int g = tid >> 7;           // group 0..3
    const int i = tid & 127;          // channel within group
    const int w = i >> 5;             // warp within group (node select)
    const int lane = tid & 31;
    float* sbg = sb + g * 4 * Hh;
    const int gg = blockIdx.x * 4 + g;
    const int base = gg * 4;          // this group's 4-node block
    const int jw = base + w;          // this warp's node

    // ---- stage 0a: T = Omega1 @ U (node-local matvec) ----
    for (int t = tid; t < Hh * Hh; t += 512) Wsm[t] = g_O1t[t];
    __syncthreads();
    {
#pragma unroll
        for (int n = 0; n < 4; n++) sbg[n * Hh + i] = g_h[(size_t)(base + n) * Hh + i];
        bar_group(g);
        float a0 = 0.f, a1 = 0.f, a2 = 0.f, a3 = 0.f;
#pragma unroll 16
        for (int m = 0; m < Hh; m++) {
            float ww = Wsm[m * Hh + i];
            a0 += ww * sbg[0 * Hh + m];
            a1 += ww * sbg[1 * Hh + m];
            a2 += ww * sbg[2 * Hh + m];
            a3 += ww * sbg[3 * Hh + m];
        }
        g_T[(size_t)(base + 0) * Hh + i] = a0;
        g_T[(size_t)(base + 1) * Hh + i] = a1;
        g_T[(size_t)(base + 2) * Hh + i] = a2;
        g_T[(size_t)(base + 3) * Hh + i] = a3;
        bar_group(g);
    }
    grid_sync(NBLK);

    // swap W in smem to Wp^T
    for (int t = tid; t < Hh * Hh; t += 512) Wsm[t] = g_Wpt[t];
    __syncthreads();

    // ---- stage 0b: B = T @ adj via warp-per-node fp32 gather ----
    {
        float4 acc = gather_row((const float4*)g_T, jw, lane);
        ((float4*)g_B)[(size_t)jw * 32 + lane] = acc;
    }

    // ---- Picard: X <- relu(Wp (X A) + B), fixed ITFIX iterations, fp16 X ----
    for (int it = 0; it < ITFIX; ++it) {
        const __half* Xr = g_Xh + (size_t)(it & 1) * Nn * Hh;
        __half* Xw = g_Xh + (size_t)((it & 1) ^ 1) * Nn * Hh;

        // gather: warp w builds y-row of node jw into smem
        {
            float4 acc = gather_row_h((const uint2*)Xr, jw, lane);
            ((float4*)sbg)[w * 32 + lane] = acc;
        }
        bar_group(g);

        // matvec: thread-per-channel i, Wsm row shared across 4 nodes
        float a0 = g_B[(size_t)(base + 0) * Hh + i];
        float a1 = g_B[(size_t)(base + 1) * Hh + i];
        float a2 = g_B[(size_t)(base + 2) * Hh + i];
        float a3 = g_B[(size_t)(base + 3) * Hh + i];
#pragma unroll 16
        for (int m = 0; m < Hh; m++) {
            float ww = Wsm[m * Hh + i];
            a0 += ww * sbg[0 * Hh + m];
            a1 += ww * sbg[1 * Hh + m];
            a2 += ww * sbg[2 * Hh + m];
            a3 += ww * sbg[3 * Hh + m];
        }
        Xw[(size_t)(base + 0) * Hh + i] = __float2half(fmaxf(a0, 0.f));
        Xw[(size_t)(base + 1) * Hh + i] = __float2half(fmaxf(a1, 0.f));
        Xw[(size_t)(base + 2) * Hh + i] = __float2half(fmaxf(a2, 0.f));
        Xw[(size_t)(base + 3) * Hh + i] = __float2half(fmaxf(a3, 0.f));
        grid_sync(NBLK);
    }

    // ---- fused epilogue: out = LN(h + X) @ W_V^T + b_V (group-local) ----
    const __half* Xf = g_Xh + 0;   // ITFIX even -> final in buffer 0
    float vn[4];
#pragma unroll
    for (int n = 0; n < 4; n++)
        vn[n] = g_h[(size_t)(base + n) * Hh + i] +
                __half2float(Xf[(size_t)(base + n) * Hh + i]);
    // per-node LN over the group's 128 channels
#pragma unroll
    for (int n = 0; n < 4; n++) {
        float s = vn[n], q = vn[n] * vn[n];
#pragma unroll
        for (int o = 16; o > 0; o >>= 1) {
            s += __shfl_xor_sync(0xffffffffu, s, o);
            q += __shfl_xor_sync(0xffffffffu, q, o);
        }
        if (lane == 0) { s_red[g][w * 8 + n] = s; s_red[g][w * 8 + 4 + n] = q; }
    }
    bar_group(g);
    float gi = lng[i], bbi = lnb[i];
#pragma unroll
    for (int n = 0; n < 4; n++) {
        float ts = s_red[g][0 * 8 + n] + s_red[g][1 * 8 + n] +
                   s_red[g][2 * 8 + n] + s_red[g][3 * 8 + n];
        float tq = s_red[g][0 * 8 + 4 + n] + s_red[g][1 * 8 + 4 + n] +
                   s_red[g][2 * 8 + 4 + n] + s_red[g][3 * 8 + 4 + n];
        float mu = ts * (1.f / 128.f);
        float var = tq * (1.f / 128.f) - mu * mu;
        sbg[n * Hh + i] = (vn[n] - mu) * rsqrtf(var + LNEPS) * gi + bbi;
    }
    bar_group(g);
    if (i < OUTd) {
        float a[4];
        float bvi = bv[i];
#pragma unroll
        for (int n = 0; n < 4; n++) a[n] = bvi;
#pragma unroll 8
        for (int m = 0; m < Hh; m++) {
            float ww = Wv[i * Hh + m];
#pragma unroll
            for (int n = 0; n < 4; n++) a[n] += ww * sbg[n * Hh + m];
        }
#pragma unroll
        for (int n = 0; n < 4; n++)
            out[(size_t)(base + n) * OUTd + i] = a[n];
    }
}

// ---------------- host launch ----------------
extern "C" void kernel_launch(void* const* d_in, const int* in_sizes, int n_in,
                              void* d_out, int out_size) {
    const float* x    = (const float*)d_in[0];
    const float* adj  = (const float*)d_in[3];
    const float* Wenc = (const float*)d_in[4];
    const float* benc = (const float*)d_in[5];
    const float* lng  = (const float*)d_in[6];
    const float* lnb  = (const float*)d_in[7];
    const float* W    = (const float*)d_in[8];
    const float* O1   = (const float*)d_in[9];
    const float* Wv   = (const float*)d_in[10];
    const float* bv   = (const float*)d_in[11];
    const float* X0   = (const float*)d_in[12];
    float* out = (float*)d_out;

    cudaFuncSetAttribute(k_fp, cudaFuncAttributeMaxDynamicSharedMemorySize, FP_SMEM);

    k_setup<<<449, 256>>>(X0, Wenc, O1);
    k_proj<<<32, 128>>>(W);
    k_scan<<<((Nn / 4) * CH) / 256, 256>>>(adj);
    k_offcmp<<<Nn / 8, 256>>>();
    k_enc<<<Nn / 16, 256>>>(x, benc, lng, lnb);
    k_fp<<<NBLK, 512, FP_SMEM>>>(Wv, bv, lng, lnb, out);
}